// round 15
// baseline (speedup 1.0000x reference)
#include <cuda_runtime.h>
#include <cuda_fp16.h>
#include <math.h>
#include <stdint.h>

#define N_BATCH 4
#define C_DIM   256
#define P_DIM   4096
#define HB      0.5f
#define EPS     1e-5f
#define LOG2E   1.4426950408889634f

// ---------------- scratch ----------------------------------------------------
__device__ float  g_mu[C_DIM];
__device__ __half g_xh[(size_t)N_BATCH * C_DIM * P_DIM];   // [n][c][p] fp16 normalized
__device__ __half g_yh[(size_t)N_BATCH * C_DIM * P_DIM];
__device__ __half g_cosh[(size_t)N_BATCH * P_DIM * P_DIM]; // 128 MB
__device__ unsigned int g_rowmax[N_BATCH * P_DIM];         // order-encoded row maxes
#define R_CHUNK 16
#define N_RCH   (P_DIM / R_CHUNK)                          // 256 row-groups per batch
#define PCH     8                                          // colB pc-split
__device__ float  g_colM[(size_t)N_BATCH * N_RCH * P_DIM]; // 16 MB partial col maxes of t
__device__ float  g_colM2[(size_t)N_BATCH * PCH * P_DIM];  // 512 KB second-level partials
__device__ float  g_cxpart[N_BATCH * 8];

__device__ __forceinline__ uint32_t smem_u32(const void* p) {
    uint32_t a;
    asm("{ .reg .u64 t; cvta.to.shared.u64 t, %1; cvt.u32.u64 %0, t; }" : "=r"(a) : "l"(p));
    return a;
}
__device__ __forceinline__ void h8_to_f(uint4 u, float* f) {
    __half2* h = (__half2*)&u;
    #pragma unroll
    for (int j = 0; j < 4; j++) {
        float2 p = __half22float2(h[j]);
        f[2 * j] = p.x; f[2 * j + 1] = p.y;
    }
}
__device__ __forceinline__ void cpasync16(uint32_t smaddr, const void* gptr) {
    asm volatile("cp.async.cg.shared.global [%0], [%1], 16;" :: "r"(smaddr), "l"(gptr));
}
// order-preserving float <-> uint (monotone); safe for atomicMax
__device__ __forceinline__ unsigned int encf(float f) {
    unsigned int b = __float_as_uint(f);
    return (b & 0x80000000u) ? ~b : (b | 0x80000000u);
}
__device__ __forceinline__ float decf(unsigned int e) {
    unsigned int b = (e & 0x80000000u) ? (e & 0x7FFFFFFFu) : ~e;
    return __uint_as_float(b);
}

// ---------------- K0: zero the row-max array ---------------------------------
__global__ void k_init() {
    g_rowmax[blockIdx.x * 256 + threadIdx.x] = 0u;   // enc of any cos>=-1 exceeds 0
}

// ---------------- K1: per-channel mean of y ----------------------------------
__global__ void k_mean(const float* __restrict__ y) {
    int c = blockIdx.x;
    int tid = threadIdx.x;
    float s = 0.f;
    for (int n = 0; n < N_BATCH; n++) {
        const float* base = y + ((size_t)n * C_DIM + c) * P_DIM;
        for (int p = tid; p < P_DIM; p += 256) s += base[p];
    }
    __shared__ float sm[256];
    sm[tid] = s; __syncthreads();
    for (int o = 128; o > 0; o >>= 1) {
        if (tid < o) sm[tid] += sm[tid + o];
        __syncthreads();
    }
    if (tid == 0) g_mu[c] = sm[0] * (1.f / (float)(N_BATCH * P_DIM));
}

// ---------------- K2: center + normalize -> fp16 (channel-parallel) ---------
__global__ __launch_bounds__(256) void k_norm(const float* __restrict__ x,
                                              const float* __restrict__ y) {
    __shared__ float mu[C_DIM];
    __shared__ float px[8][32];
    __shared__ float py[8][32];

    int tid = threadIdx.x;
    if (tid < C_DIM) mu[tid] = g_mu[tid];

    int pl = tid & 31, cg = tid >> 5;
    int blk = blockIdx.x;                       // 0 .. N*P/32-1
    int n = blk >> 7;                           // blk / 128
    int p = ((blk & 127) << 5) + pl;            // (blk%128)*32 + pl
    __syncthreads();

    const float* xb = x + ((size_t)n * C_DIM + cg * 32) * P_DIM + p;
    const float* yb = y + ((size_t)n * C_DIM + cg * 32) * P_DIM + p;

    float xv[32], yv[32];
    float sx = 0.f, sy = 0.f;
    #pragma unroll
    for (int i = 0; i < 32; i++) {
        float m = mu[cg * 32 + i];
        float a = xb[(size_t)i * P_DIM] - m;
        float b = yb[(size_t)i * P_DIM] - m;
        xv[i] = a; yv[i] = b;
        sx += a * a; sy += b * b;
    }
    px[cg][pl] = sx;
    py[cg][pl] = sy;
    __syncthreads();

    float tx = 0.f, ty = 0.f;
    #pragma unroll
    for (int w = 0; w < 8; w++) { tx += px[w][pl]; ty += py[w][pl]; }
    float rx = rsqrtf(tx), ry = rsqrtf(ty);

    __half* xo = g_xh + ((size_t)n * C_DIM + cg * 32) * P_DIM + p;
    __half* yo = g_yh + ((size_t)n * C_DIM + cg * 32) * P_DIM + p;
    #pragma unroll
    for (int i = 0; i < 32; i++) {
        xo[(size_t)i * P_DIM] = __float2half_rn(xv[i] * rx);
        yo[(size_t)i * P_DIM] = __float2half_rn(yv[i] * ry);
    }
}

// ---------------- K3: fp16 mma GEMM + fused row-max atomics ------------------
#define BM 128
#define BN 128
#define BK 32
#define STG 8192      // bytes per A (or B) stage: 32 k * 128 * 2B

__device__ __forceinline__ void mma_f16acc(uint32_t* c, const uint32_t* a, const uint32_t* b) {
    asm volatile(
        "mma.sync.aligned.m16n8k16.row.col.f16.f16.f16.f16 "
        "{%0,%1},{%2,%3,%4,%5},{%6,%7},{%0,%1};\n"
        : "+r"(c[0]), "+r"(c[1])
        : "r"(a[0]), "r"(a[1]), "r"(a[2]), "r"(a[3]), "r"(b[0]), "r"(b[1]));
}
__device__ __forceinline__ void ldsm4t(uint32_t* r, uint32_t addr) {
    asm volatile("ldmatrix.sync.aligned.m8n8.x4.trans.shared.b16 {%0,%1,%2,%3},[%4];"
                 : "=r"(r[0]), "=r"(r[1]), "=r"(r[2]), "=r"(r[3]) : "r"(addr));
}

__global__ __launch_bounds__(128, 4) void k_gemm_h() {
    __shared__ char sm[6 * STG];    // A0 A1 A2 B0 B1 B2 = 48 KB

    int nb = blockIdx.z;
    const __half* A = g_xh + (size_t)nb * C_DIM * P_DIM;
    const __half* B = g_yh + (size_t)nb * C_DIM * P_DIM;
    __half* Cm      = g_cosh + (size_t)nb * P_DIM * P_DIM;
    unsigned int* rmax = g_rowmax + nb * P_DIM;

    int tid = threadIdx.x;
    int m0 = blockIdx.x * BM, n0 = blockIdx.y * BN;
    int warp = tid >> 5, lane = tid & 31;
    int wm = warp & 1, wn = warp >> 1;
    int g = lane >> 2, t = lane & 3;
    int lg = lane >> 3, lr = lane & 7;

    uint32_t smbase = smem_u32(sm);
    uint32_t smA[3] = { smbase, smbase + STG, smbase + 2 * STG };
    uint32_t smB[3] = { smbase + 3 * STG, smbase + 4 * STG, smbase + 5 * STG };

    int lk[4], lj[4];
    uint32_t soff[4];
    #pragma unroll
    for (int v = 0; v < 4; v++) {
        int idx = v * 128 + tid;
        lk[v] = idx >> 4;
        lj[v] = idx & 15;
        soff[v] = lk[v] * 256 + ((lj[v] ^ (lk[v] & 7)) << 4);
    }

    const int NST = C_DIM / BK;    // 8

    #define ISSUE(st, sb)                                                          \
    {                                                                              \
        size_t koff_ = (size_t)(st) * BK * P_DIM;                                  \
        _Pragma("unroll")                                                          \
        for (int v = 0; v < 4; v++) {                                              \
            cpasync16(smA[sb] + soff[v], A + koff_ + (size_t)lk[v] * P_DIM + m0 + lj[v] * 8); \
            cpasync16(smB[sb] + soff[v], B + koff_ + (size_t)lk[v] * P_DIM + n0 + lj[v] * 8); \
        }                                                                          \
        asm volatile("cp.async.commit_group;");                                    \
    }

    uint32_t acc[4][8][2] = {};   // half2-packed fp16 accumulators

    ISSUE(0, 0);
    ISSUE(1, 1);

    #pragma unroll 1
    for (int st = 0; st < NST; st++) {
        asm volatile("cp.async.wait_group 1;" ::: "memory");
        __syncthreads();
        // single barrier: ISSUE targets slot (st+2)%3 == (st-1)%3, which all
        // warps finished before passing the barrier above.
        if (st + 2 < NST) ISSUE(st + 2, (st + 2) % 3);
        int buf = st % 3;

        #pragma unroll
        for (int ks = 0; ks < BK; ks += 16) {
            uint32_t af[4][4], bf[8][2];
            int ak = ks + lr + ((lg >> 1) << 3);
            #pragma unroll
            for (int im = 0; im < 4; im++) {
                int mj = wm * 8 + im * 2 + (lg & 1);
                ldsm4t(af[im], smA[buf] + ak * 256 + ((mj ^ (ak & 7)) << 4));
            }
            int bk = ks + lr + ((lg & 1) << 3);
            #pragma unroll
            for (int jp = 0; jp < 4; jp++) {
                int njc = wn * 8 + jp * 2 + (lg >> 1);
                uint32_t r[4];
                ldsm4t(r, smB[buf] + bk * 256 + ((njc ^ (bk & 7)) << 4));
                bf[jp * 2][0] = r[0]; bf[jp * 2][1] = r[1];
                bf[jp * 2 + 1][0] = r[2]; bf[jp * 2 + 1][1] = r[3];
            }
            #pragma unroll
            for (int im = 0; im < 4; im++)
                #pragma unroll
                for (int jn = 0; jn < 8; jn++)
                    mma_f16acc(acc[im][jn], af[im], bf[jn]);
        }
    }

    // epilogue: store half2 accs + fused per-row max atomics
    #pragma unroll
    for (int im = 0; im < 4; im++) {
        int m = m0 + wm * 64 + im * 16 + g;
        __half2 mx0 = *(__half2*)&acc[im][0][0];
        __half2 mx1 = *(__half2*)&acc[im][0][1];
        #pragma unroll
        for (int jn = 0; jn < 8; jn++) {
            int n = n0 + wn * 64 + jn * 8 + t * 2;
            *(uint32_t*)&Cm[(size_t)m * P_DIM + n]       = acc[im][jn][0];
            *(uint32_t*)&Cm[(size_t)(m + 8) * P_DIM + n] = acc[im][jn][1];
            if (jn) {
                mx0 = __hmax2(mx0, *(__half2*)&acc[im][jn][0]);
                mx1 = __hmax2(mx1, *(__half2*)&acc[im][jn][1]);
            }
        }
        float f0 = fmaxf(__low2float(mx0), __high2float(mx0));
        float f1 = fmaxf(__low2float(mx1), __high2float(mx1));
        atomicMax(&rmax[m],     encf(f0));
        atomicMax(&rmax[m + 8], encf(f1));
    }
}

// ---------------- K4: fused row-sum + column-max (max precomputed) -----------
__global__ __launch_bounds__(256) void k_rowcol() {
    int blk = blockIdx.x;              // 0 .. N*P/16-1
    int tid = threadIdx.x;
    int warp = tid >> 5, lane = tid & 31;
    int row0 = blk * R_CHUNK;

    __shared__ float red[2][8];        // warp sums, row-parity buffered

    float colmax[16];
    #pragma unroll
    for (int i = 0; i < 16; i++) colmax[i] = -1e30f;

    // prefetch row 0
    const uint4* r4 = (const uint4*)(g_cosh + (size_t)row0 * P_DIM);
    uint4 c0 = r4[tid], c1 = r4[tid + 256];

    #pragma unroll 1
    for (int r = 0; r < R_CHUNK; r++) {
        // issue next row's loads before consuming this row
        uint4 n0_, n1_;
        if (r + 1 < R_CHUNK) {
            const uint4* r4n = (const uint4*)(g_cosh + (size_t)(row0 + r + 1) * P_DIM);
            n0_ = r4n[tid]; n1_ = r4n[tid + 256];
        }

        float m = decf(g_rowmax[row0 + r]);          // broadcast load
        float b2 = LOG2E / (HB * ((1.f - m) + EPS));
        float nb2m = -b2 * m;

        float v[16];
        h8_to_f(c0, v);
        h8_to_f(c1, v + 8);

        float u[16];
        float s = 0.f;
        #pragma unroll
        for (int i = 0; i < 16; i++) {
            u[i] = fmaf(b2, v[i], nb2m);             // t-premax = b2*(v-m)
            s += exp2f(u[i]);
        }
        #pragma unroll
        for (int o = 16; o > 0; o >>= 1)
            s += __shfl_xor_sync(0xffffffffu, s, o);
        int par = r & 1;
        if (lane == 0) red[par][warp] = s;
        __syncthreads();
        s = red[par][0];
        #pragma unroll
        for (int w = 1; w < 8; w++) s += red[par][w];

        float nls = -log2f(s);
        #pragma unroll
        for (int i = 0; i < 16; i++)
            colmax[i] = fmaxf(colmax[i], u[i] + nls);

        c0 = n0_; c1 = n1_;
    }

    float* out = g_colM + (size_t)blk * P_DIM;
    *(float4*)&out[tid * 8]            = make_float4(colmax[0], colmax[1], colmax[2], colmax[3]);
    *(float4*)&out[tid * 8 + 4]        = make_float4(colmax[4], colmax[5], colmax[6], colmax[7]);
    *(float4*)&out[2048 + tid * 8]     = make_float4(colmax[8],  colmax[9],  colmax[10], colmax[11]);
    *(float4*)&out[2048 + tid * 8 + 4] = make_float4(colmax[12], colmax[13], colmax[14], colmax[15]);
}

// ---------------- K5a: col max over pc chunk (grid 8 x N x PCH) --------------
__global__ __launch_bounds__(256) void k_colB() {
    int n = blockIdx.y;
    int zc = blockIdx.z;                              // pc chunk 0..7
    int q0 = (blockIdx.x * 256 + threadIdx.x) * 2;    // grid.x = 8
    const int PCC = N_RCH / PCH;                      // 32 row-groups per chunk
    const float* cmn = g_colM + (size_t)n * N_RCH * P_DIM;

    float M0 = -1e30f, M1 = -1e30f;
    #pragma unroll 4
    for (int pc = zc * PCC; pc < (zc + 1) * PCC; pc++) {
        float2 v = *(const float2*)&cmn[(size_t)pc * P_DIM + q0];
        M0 = fmaxf(M0, v.x);
        M1 = fmaxf(M1, v.y);
    }
    *(float2*)&g_colM2[((size_t)n * PCH + zc) * P_DIM + q0] = make_float2(M0, M1);
}

// ---------------- K5b: finish col max, one exp2 per q, sum -------------------
__global__ __launch_bounds__(256) void k_colC() {
    int n = blockIdx.y;
    int q0 = (blockIdx.x * 256 + threadIdx.x) * 2;    // grid.x = 8
    const float* cmn = g_colM2 + (size_t)n * PCH * P_DIM;
    float M0 = -1e30f, M1 = -1e30f;
    #pragma unroll
    for (int z = 0; z < PCH; z++) {
        float2 v = *(const float2*)&cmn[(size_t)z * P_DIM + q0];
        M0 = fmaxf(M0, v.x);
        M1 = fmaxf(M1, v.y);
    }
    float s = exp2f(M0) + exp2f(M1);

    __shared__ float red[256];
    red[threadIdx.x] = s; __syncthreads();
    for (int o = 128; o > 0; o >>= 1) {
        if (threadIdx.x < o) red[threadIdx.x] += red[threadIdx.x + o];
        __syncthreads();
    }
    if (threadIdx.x == 0)
        g_cxpart[n * 8 + blockIdx.x] = red[0];
}

// ---------------- K6: final scalar loss --------------------------------------
__global__ void k_final(float* __restrict__ out) {
    if (threadIdx.x == 0) {
        float loss = 0.f;
        for (int n = 0; n < N_BATCH; n++) {
            float s = 0.f;
            for (int b = 0; b < 8; b++) s += g_cxpart[n * 8 + b];
            float cx = s * (1.f / (float)P_DIM);
            loss += -logf(cx + EPS);
        }
        out[0] = loss * (1.f / (float)N_BATCH);
    }
}

// ---------------- launch ------------------------------------------------------
extern "C" void kernel_launch(void* const* d_in, const int* in_sizes, int n_in,
                              void* d_out, int out_size) {
    const float* x = (const float*)d_in[0];
    const float* y = (const float*)d_in[1];
    float* out = (float*)d_out;

    k_init<<<(N_BATCH * P_DIM) / 256, 256>>>();
    k_mean<<<C_DIM, 256>>>(y);
    k_norm<<<(N_BATCH * P_DIM) / 32, 256>>>(x, y);

    dim3 gg(P_DIM / BM, P_DIM / BN, N_BATCH);
    k_gemm_h<<<gg, 128>>>();

    k_rowcol<<<(N_BATCH * P_DIM) / R_CHUNK, 256>>>();

    dim3 gcb(P_DIM / 512, N_BATCH, PCH);
    k_colB<<<gcb, 256>>>();

    dim3 gcc(P_DIM / 512, N_BATCH);
    k_colC<<<gcc, 256>>>();

    k_final<<<1, 32>>>(out);
}

// round 16
// speedup vs baseline: 1.0418x; 1.0418x over previous
#include <cuda_runtime.h>
#include <cuda_fp16.h>
#include <math.h>
#include <stdint.h>

#define N_BATCH 4
#define C_DIM   256
#define P_DIM   4096
#define HB      0.5f
#define EPS     1e-5f
#define LOG2E   1.4426950408889634f

// ---------------- scratch ----------------------------------------------------
#define MCH 8
__device__ float  g_mupart[C_DIM * MCH];
__device__ float  g_mu[C_DIM];
__device__ __half g_xh[(size_t)N_BATCH * C_DIM * P_DIM];   // [n][c][p] fp16 normalized
__device__ __half g_yh[(size_t)N_BATCH * C_DIM * P_DIM];
__device__ __half g_cosh[(size_t)N_BATCH * P_DIM * P_DIM]; // 128 MB
__device__ unsigned int g_rowmax[N_BATCH * P_DIM];         // order-encoded row maxes
#define R_CHUNK 16
#define N_RCH   (P_DIM / R_CHUNK)                          // 256 row-groups per batch
#define PCH     8                                          // colB pc-split
__device__ float  g_colM[(size_t)N_BATCH * N_RCH * P_DIM]; // 16 MB partial col maxes of t
__device__ float  g_colM2[(size_t)N_BATCH * PCH * P_DIM];  // 512 KB second-level partials
__device__ float  g_cxpart[N_BATCH * 8];

__device__ __forceinline__ uint32_t smem_u32(const void* p) {
    uint32_t a;
    asm("{ .reg .u64 t; cvta.to.shared.u64 t, %1; cvt.u32.u64 %0, t; }" : "=r"(a) : "l"(p));
    return a;
}
__device__ __forceinline__ void h8_to_f(uint4 u, float* f) {
    __half2* h = (__half2*)&u;
    #pragma unroll
    for (int j = 0; j < 4; j++) {
        float2 p = __half22float2(h[j]);
        f[2 * j] = p.x; f[2 * j + 1] = p.y;
    }
}
__device__ __forceinline__ void cpasync16(uint32_t smaddr, const void* gptr) {
    asm volatile("cp.async.cg.shared.global [%0], [%1], 16;" :: "r"(smaddr), "l"(gptr));
}
// order-preserving float <-> uint (monotone); safe for atomicMax
__device__ __forceinline__ unsigned int encf(float f) {
    unsigned int b = __float_as_uint(f);
    return (b & 0x80000000u) ? ~b : (b | 0x80000000u);
}
__device__ __forceinline__ float decf(unsigned int e) {
    unsigned int b = (e & 0x80000000u) ? (e & 0x7FFFFFFFu) : ~e;
    return __uint_as_float(b);
}

// ---------------- K1a: partial channel sums of y (c x chunk grid) ------------
__global__ __launch_bounds__(256) void k_mean1(const float* __restrict__ y) {
    int c  = blockIdx.x;
    int ch = blockIdx.y;                       // 0..MCH-1
    int tid = threadIdx.x;
    const int CHW = P_DIM / MCH;               // 512 elems per chunk per (n)
    float s = 0.f;
    #pragma unroll
    for (int n = 0; n < N_BATCH; n++) {
        const float* base = y + ((size_t)n * C_DIM + c) * P_DIM + ch * CHW;
        #pragma unroll 2
        for (int p = tid; p < CHW; p += 256) s += base[p];
    }
    __shared__ float sm[256];
    sm[tid] = s; __syncthreads();
    for (int o = 128; o > 0; o >>= 1) {
        if (tid < o) sm[tid] += sm[tid + o];
        __syncthreads();
    }
    if (tid == 0) g_mupart[c * MCH + ch] = sm[0];
}

// ---------------- K1b: finish means ------------------------------------------
__global__ void k_mean2() {
    int c = blockIdx.x * 32 + threadIdx.x;     // grid 8 x 32
    float s = 0.f;
    #pragma unroll
    for (int ch = 0; ch < MCH; ch++) s += g_mupart[c * MCH + ch];
    g_mu[c] = s * (1.f / (float)(N_BATCH * P_DIM));
}

// ---------------- K2: center + normalize -> fp16 (+ rowmax zeroing) ----------
__global__ __launch_bounds__(256) void k_norm(const float* __restrict__ x,
                                              const float* __restrict__ y) {
    __shared__ float mu[C_DIM];
    __shared__ float px[8][32];
    __shared__ float py[8][32];

    int tid = threadIdx.x;
    if (tid < C_DIM) mu[tid] = g_mu[tid];

    int pl = tid & 31, cg = tid >> 5;
    int blk = blockIdx.x;                       // 0 .. N*P/32-1
    int n = blk >> 7;                           // blk / 128
    int p = ((blk & 127) << 5) + pl;            // (blk%128)*32 + pl

    // fold k_init: zero this block's 32 rowmax entries (before gemm launches)
    if (tid < 32) g_rowmax[blk * 32 + tid] = 0u;
    __syncthreads();

    const float* xb = x + ((size_t)n * C_DIM + cg * 32) * P_DIM + p;
    const float* yb = y + ((size_t)n * C_DIM + cg * 32) * P_DIM + p;

    float xv[32], yv[32];
    float sx = 0.f, sy = 0.f;
    #pragma unroll
    for (int i = 0; i < 32; i++) {
        float m = mu[cg * 32 + i];
        float a = xb[(size_t)i * P_DIM] - m;
        float b = yb[(size_t)i * P_DIM] - m;
        xv[i] = a; yv[i] = b;
        sx += a * a; sy += b * b;
    }
    px[cg][pl] = sx;
    py[cg][pl] = sy;
    __syncthreads();

    float tx = 0.f, ty = 0.f;
    #pragma unroll
    for (int w = 0; w < 8; w++) { tx += px[w][pl]; ty += py[w][pl]; }
    float rx = rsqrtf(tx), ry = rsqrtf(ty);

    __half* xo = g_xh + ((size_t)n * C_DIM + cg * 32) * P_DIM + p;
    __half* yo = g_yh + ((size_t)n * C_DIM + cg * 32) * P_DIM + p;
    #pragma unroll
    for (int i = 0; i < 32; i++) {
        xo[(size_t)i * P_DIM] = __float2half_rn(xv[i] * rx);
        yo[(size_t)i * P_DIM] = __float2half_rn(yv[i] * ry);
    }
}

// ---------------- K3: fp16 mma GEMM + fused row-max atomics ------------------
#define BM 128
#define BN 128
#define BK 32
#define STG 8192      // bytes per A (or B) stage: 32 k * 128 * 2B

__device__ __forceinline__ void mma_f16acc(uint32_t* c, const uint32_t* a, const uint32_t* b) {
    asm volatile(
        "mma.sync.aligned.m16n8k16.row.col.f16.f16.f16.f16 "
        "{%0,%1},{%2,%3,%4,%5},{%6,%7},{%0,%1};\n"
        : "+r"(c[0]), "+r"(c[1])
        : "r"(a[0]), "r"(a[1]), "r"(a[2]), "r"(a[3]), "r"(b[0]), "r"(b[1]));
}
__device__ __forceinline__ void ldsm4t(uint32_t* r, uint32_t addr) {
    asm volatile("ldmatrix.sync.aligned.m8n8.x4.trans.shared.b16 {%0,%1,%2,%3},[%4];"
                 : "=r"(r[0]), "=r"(r[1]), "=r"(r[2]), "=r"(r[3]) : "r"(addr));
}

__global__ __launch_bounds__(128, 4) void k_gemm_h() {
    __shared__ char sm[6 * STG];    // A0 A1 A2 B0 B1 B2 = 48 KB

    int nb = blockIdx.z;
    const __half* A = g_xh + (size_t)nb * C_DIM * P_DIM;
    const __half* B = g_yh + (size_t)nb * C_DIM * P_DIM;
    __half* Cm      = g_cosh + (size_t)nb * P_DIM * P_DIM;
    unsigned int* rmax = g_rowmax + nb * P_DIM;

    int tid = threadIdx.x;
    int m0 = blockIdx.x * BM, n0 = blockIdx.y * BN;
    int warp = tid >> 5, lane = tid & 31;
    int wm = warp & 1, wn = warp >> 1;
    int g = lane >> 2, t = lane & 3;
    int lg = lane >> 3, lr = lane & 7;

    uint32_t smbase = smem_u32(sm);
    uint32_t smA[3] = { smbase, smbase + STG, smbase + 2 * STG };
    uint32_t smB[3] = { smbase + 3 * STG, smbase + 4 * STG, smbase + 5 * STG };

    int lk[4], lj[4];
    uint32_t soff[4];
    #pragma unroll
    for (int v = 0; v < 4; v++) {
        int idx = v * 128 + tid;
        lk[v] = idx >> 4;
        lj[v] = idx & 15;
        soff[v] = lk[v] * 256 + ((lj[v] ^ (lk[v] & 7)) << 4);
    }

    const int NST = C_DIM / BK;    // 8

    #define ISSUE(st, sb)                                                          \
    {                                                                              \
        size_t koff_ = (size_t)(st) * BK * P_DIM;                                  \
        _Pragma("unroll")                                                          \
        for (int v = 0; v < 4; v++) {                                              \
            cpasync16(smA[sb] + soff[v], A + koff_ + (size_t)lk[v] * P_DIM + m0 + lj[v] * 8); \
            cpasync16(smB[sb] + soff[v], B + koff_ + (size_t)lk[v] * P_DIM + n0 + lj[v] * 8); \
        }                                                                          \
        asm volatile("cp.async.commit_group;");                                    \
    }

    uint32_t acc[4][8][2] = {};   // half2-packed fp16 accumulators

    ISSUE(0, 0);
    ISSUE(1, 1);

    #pragma unroll 1
    for (int st = 0; st < NST; st++) {
        asm volatile("cp.async.wait_group 1;" ::: "memory");
        __syncthreads();
        if (st + 2 < NST) ISSUE(st + 2, (st + 2) % 3);
        int buf = st % 3;

        #pragma unroll
        for (int ks = 0; ks < BK; ks += 16) {
            uint32_t af[4][4], bf[8][2];
            int ak = ks + lr + ((lg >> 1) << 3);
            #pragma unroll
            for (int im = 0; im < 4; im++) {
                int mj = wm * 8 + im * 2 + (lg & 1);
                ldsm4t(af[im], smA[buf] + ak * 256 + ((mj ^ (ak & 7)) << 4));
            }
            int bk = ks + lr + ((lg & 1) << 3);
            #pragma unroll
            for (int jp = 0; jp < 4; jp++) {
                int njc = wn * 8 + jp * 2 + (lg >> 1);
                uint32_t r[4];
                ldsm4t(r, smB[buf] + bk * 256 + ((njc ^ (bk & 7)) << 4));
                bf[jp * 2][0] = r[0]; bf[jp * 2][1] = r[1];
                bf[jp * 2 + 1][0] = r[2]; bf[jp * 2 + 1][1] = r[3];
            }
            #pragma unroll
            for (int im = 0; im < 4; im++)
                #pragma unroll
                for (int jn = 0; jn < 8; jn++)
                    mma_f16acc(acc[im][jn], af[im], bf[jn]);
        }
    }

    // epilogue: store half2 accs + fused per-row max atomics
    #pragma unroll
    for (int im = 0; im < 4; im++) {
        int m = m0 + wm * 64 + im * 16 + g;
        __half2 mx0 = *(__half2*)&acc[im][0][0];
        __half2 mx1 = *(__half2*)&acc[im][0][1];
        #pragma unroll
        for (int jn = 0; jn < 8; jn++) {
            int n = n0 + wn * 64 + jn * 8 + t * 2;
            *(uint32_t*)&Cm[(size_t)m * P_DIM + n]       = acc[im][jn][0];
            *(uint32_t*)&Cm[(size_t)(m + 8) * P_DIM + n] = acc[im][jn][1];
            if (jn) {
                mx0 = __hmax2(mx0, *(__half2*)&acc[im][jn][0]);
                mx1 = __hmax2(mx1, *(__half2*)&acc[im][jn][1]);
            }
        }
        float f0 = fmaxf(__low2float(mx0), __high2float(mx0));
        float f1 = fmaxf(__low2float(mx1), __high2float(mx1));
        atomicMax(&rmax[m],     encf(f0));
        atomicMax(&rmax[m + 8], encf(f1));
    }
}

// ---------------- K4: fused row-sum + column-max (low-reg version) -----------
__global__ __launch_bounds__(256) void k_rowcol() {
    int blk = blockIdx.x;              // 0 .. N*P/16-1
    int tid = threadIdx.x;
    int warp = tid >> 5, lane = tid & 31;
    int row0 = blk * R_CHUNK;

    __shared__ float red[2][8];        // warp sums, row-parity buffered

    float colmax[16];
    #pragma unroll
    for (int i = 0; i < 16; i++) colmax[i] = -1e30f;

    // prefetch row 0
    const uint4* r4 = (const uint4*)(g_cosh + (size_t)row0 * P_DIM);
    uint4 c0 = r4[tid], c1 = r4[tid + 256];

    #pragma unroll 1
    for (int r = 0; r < R_CHUNK; r++) {
        uint4 n0_, n1_;
        if (r + 1 < R_CHUNK) {
            const uint4* r4n = (const uint4*)(g_cosh + (size_t)(row0 + r + 1) * P_DIM);
            n0_ = r4n[tid]; n1_ = r4n[tid + 256];
        }

        float m = decf(g_rowmax[row0 + r]);          // broadcast load
        float b2 = LOG2E / (HB * ((1.f - m) + EPS));
        float nb2m = -b2 * m;

        float v[16];
        h8_to_f(c0, v);
        h8_to_f(c1, v + 8);

        float s = 0.f;
        #pragma unroll
        for (int i = 0; i < 16; i++)
            s += exp2f(fmaf(b2, v[i], nb2m));
        #pragma unroll
        for (int o = 16; o > 0; o >>= 1)
            s += __shfl_xor_sync(0xffffffffu, s, o);
        int par = r & 1;
        if (lane == 0) red[par][warp] = s;
        __syncthreads();
        s = red[par][0];
        #pragma unroll
        for (int w = 1; w < 8; w++) s += red[par][w];

        float bias = nb2m - log2f(s);
        #pragma unroll
        for (int i = 0; i < 16; i++)
            colmax[i] = fmaxf(colmax[i], fmaf(b2, v[i], bias));

        c0 = n0_; c1 = n1_;
    }

    float* out = g_colM + (size_t)blk * P_DIM;
    *(float4*)&out[tid * 8]            = make_float4(colmax[0], colmax[1], colmax[2], colmax[3]);
    *(float4*)&out[tid * 8 + 4]        = make_float4(colmax[4], colmax[5], colmax[6], colmax[7]);
    *(float4*)&out[2048 + tid * 8]     = make_float4(colmax[8],  colmax[9],  colmax[10], colmax[11]);
    *(float4*)&out[2048 + tid * 8 + 4] = make_float4(colmax[12], colmax[13], colmax[14], colmax[15]);
}

// ---------------- K5a: col max over pc chunk (grid 8 x N x PCH) --------------
__global__ __launch_bounds__(256) void k_colB() {
    int n = blockIdx.y;
    int zc = blockIdx.z;                              // pc chunk 0..7
    int q0 = (blockIdx.x * 256 + threadIdx.x) * 2;    // grid.x = 8
    const int PCC = N_RCH / PCH;                      // 32 row-groups per chunk
    const float* cmn = g_colM + (size_t)n * N_RCH * P_DIM;

    float M0 = -1e30f, M1 = -1e30f;
    #pragma unroll 4
    for (int pc = zc * PCC; pc < (zc + 1) * PCC; pc++) {
        float2 v = *(const float2*)&cmn[(size_t)pc * P_DIM + q0];
        M0 = fmaxf(M0, v.x);
        M1 = fmaxf(M1, v.y);
    }
    *(float2*)&g_colM2[((size_t)n * PCH + zc) * P_DIM + q0] = make_float2(M0, M1);
}

// ---------------- K5b: finish col max, one exp2 per q, sum -------------------
__global__ __launch_bounds__(256) void k_colC() {
    int n = blockIdx.y;
    int q0 = (blockIdx.x * 256 + threadIdx.x) * 2;    // grid.x = 8
    const float* cmn = g_colM2 + (size_t)n * PCH * P_DIM;
    float M0 = -1e30f, M1 = -1e30f;
    #pragma unroll
    for (int z = 0; z < PCH; z++) {
        float2 v = *(const float2*)&cmn[(size_t)z * P_DIM + q0];
        M0 = fmaxf(M0, v.x);
        M1 = fmaxf(M1, v.y);
    }
    float s = exp2f(M0) + exp2f(M1);

    __shared__ float red[256];
    red[threadIdx.x] = s; __syncthreads();
    for (int o = 128; o > 0; o >>= 1) {
        if (threadIdx.x < o) red[threadIdx.x] += red[threadIdx.x + o];
        __syncthreads();
    }
    if (threadIdx.x == 0)
        g_cxpart[n * 8 + blockIdx.x] = red[0];
}

// ---------------- K6: final scalar loss --------------------------------------
__global__ void k_final(float* __restrict__ out) {
    if (threadIdx.x == 0) {
        float loss = 0.f;
        for (int n = 0; n < N_BATCH; n++) {
            float s = 0.f;
            for (int b = 0; b < 8; b++) s += g_cxpart[n * 8 + b];
            float cx = s * (1.f / (float)P_DIM);
            loss += -logf(cx + EPS);
        }
        out[0] = loss * (1.f / (float)N_BATCH);
    }
}

// ---------------- launch ------------------------------------------------------
extern "C" void kernel_launch(void* const* d_in, const int* in_sizes, int n_in,
                              void* d_out, int out_size) {
    const float* x = (const float*)d_in[0];
    const float* y = (const float*)d_in[1];
    float* out = (float*)d_out;

    dim3 gm1(C_DIM, MCH);
    k_mean1<<<gm1, 256>>>(y);
    k_mean2<<<C_DIM / 32, 32>>>();
    k_norm<<<(N_BATCH * P_DIM) / 32, 256>>>(x, y);

    dim3 gg(P_DIM / BM, P_DIM / BN, N_BATCH);
    k_gemm_h<<<gg, 128>>>();

    k_rowcol<<<(N_BATCH * P_DIM) / R_CHUNK, 256>>>();

    dim3 gcb(P_DIM / 512, N_BATCH, PCH);
    k_colB<<<gcb, 256>>>();

    dim3 gcc(P_DIM / 512, N_BATCH);
    k_colC<<<gcc, 256>>>();

    k_final<<<1, 32>>>(out);
}